// round 15
// baseline (speedup 1.0000x reference)
#include <cuda_runtime.h>
#include <cuda_bf16.h>

#define B_    8
#define NUM_  128
#define L_    (NUM_ * NUM_)     // 16384
#define H_    8
#define TOPK_ 4
#define NROWS_ (B_ * NUM_)      // 1024 (b,i) rows
#define NQ_    4                // quarters per row (32 j each)

// Scratch (allocation-free rule: __device__ globals)
// Candidate = packed u64: (float_bits(value) << 32) | (127 - j).
// value >= 0 (post-ReLU) so float bits are monotone; low word ties -> smaller j.
__device__ unsigned long long g_cand[NROWS_ * H_ * NQ_ * TOPK_];  // 512 KB
__device__ unsigned long long g_maskbits[2];                      // 128-bit column mask

// ---------------------------------------------------------------------------
// Kernel 1: block = (b,i,quarter), grid 4096 (the best-total shape: R4/R5).
// Cosine+relu for 32 j x 8 h, multiply by roi, write DIRECTLY to out,
// emit per-head per-quarter top-4 packed candidates (branchless u64 warp-max).
// ---------------------------------------------------------------------------
__global__ __launch_bounds__(256, 6) void fused_kernel(
    const float4* __restrict__ q4, const float4* __restrict__ k4,
    const float* __restrict__ roi, float* __restrict__ out)
{
    __shared__ float s_attn[32 * 9];            // local j x head, pitch 9

    const int blk  = blockIdx.x;
    const int bi   = blk >> 2;                  // (b,i) row
    const int qtr  = blk & 3;                   // 32-j quarter
    const int tid  = threadIdx.x;
    const int warp = tid >> 5;
    const int lane = tid & 31;
    const int head = lane >> 2;
    const int sub  = lane & 3;

    if (blk == 0 && tid < 2) g_maskbits[tid] = 0ull;  // reset per replay
                                                      // (launch-boundary ordered)
    const size_t rowBase = (size_t)bi * (NUM_ * 128) + (size_t)qtr * (32 * 128);

    #pragma unroll
    for (int jj = 0; jj < 4; jj += 2) {
        const int jl0 = warp * 4 + jj;          // local j in [0,32)
        const size_t base0 = rowBase + (size_t)jl0 * 128;
        const size_t base1 = base0 + 128;

        float dot0 = 0.f, qq0 = 0.f, kk0 = 0.f;
        float dot1 = 0.f, qq1 = 0.f, kk1 = 0.f;
        #pragma unroll
        for (int t = 0; t < 4; ++t) {
            const int idx = head * 16 + t * 4 + sub;
            const float4 qa = __ldcs(&q4[base0 + idx]);
            const float4 ka = __ldcs(&k4[base0 + idx]);
            const float4 qb = __ldcs(&q4[base1 + idx]);
            const float4 kb = __ldcs(&k4[base1 + idx]);
            dot0 += qa.x*ka.x + qa.y*ka.y + qa.z*ka.z + qa.w*ka.w;
            qq0  += qa.x*qa.x + qa.y*qa.y + qa.z*qa.z + qa.w*qa.w;
            kk0  += ka.x*ka.x + ka.y*ka.y + ka.z*ka.z + ka.w*ka.w;
            dot1 += qb.x*kb.x + qb.y*kb.y + qb.z*kb.z + qb.w*kb.w;
            qq1  += qb.x*qb.x + qb.y*qb.y + qb.z*qb.z + qb.w*qb.w;
            kk1  += kb.x*kb.x + kb.y*kb.y + kb.z*kb.z + kb.w*kb.w;
        }
        #pragma unroll
        for (int off = 1; off <= 2; off <<= 1) {
            dot0 += __shfl_xor_sync(0xffffffffu, dot0, off);
            qq0  += __shfl_xor_sync(0xffffffffu, qq0,  off);
            kk0  += __shfl_xor_sync(0xffffffffu, kk0,  off);
            dot1 += __shfl_xor_sync(0xffffffffu, dot1, off);
            qq1  += __shfl_xor_sync(0xffffffffu, qq1,  off);
            kk1  += __shfl_xor_sync(0xffffffffu, kk1,  off);
        }
        if (sub == 0) {
            float d0 = fmaxf(sqrtf(qq0) * sqrtf(kk0), 1e-8f);
            float d1 = fmaxf(sqrtf(qq1) * sqrtf(kk1), 1e-8f);
            s_attn[jl0 * 9 + head]       = fmaxf(dot0 / d0, 0.0f);
            s_attn[(jl0 + 1) * 9 + head] = fmaxf(dot1 / d1, 0.0f);
        }
    }
    __syncthreads();

    // ---- writeback: out[b,i,j,h] = attn * roi[b,i,j] (mask applied later) ----
    {
        const int jl = tid >> 3;                          // local j (0..31)
        const float s = __ldg(&roi[bi * NUM_ + qtr * 32 + jl]);
        const size_t gbase = (size_t)bi * (NUM_ * H_) + (size_t)qtr * (32 * H_);
        out[gbase + tid] = s_attn[jl * 9 + (tid & 7)] * s;
    }

    // ---- per-head top-4 within this quarter (packed u64, branchless) ----
    {
        const float v = s_attn[lane * 9 + warp];          // conflict-free (pitch 9)
        const int jglob = qtr * 32 + lane;
        unsigned long long key =
            ((unsigned long long)__float_as_uint(v) << 32)
          | (unsigned long long)(unsigned)(127 - jglob);

        const int rbase = ((bi * H_ + warp) * NQ_ + qtr) * TOPK_;
        #pragma unroll
        for (int r = 0; r < TOPK_; ++r) {
            unsigned long long bk = key;
            #pragma unroll
            for (int off = 16; off > 0; off >>= 1) {
                const unsigned long long ok = __shfl_xor_sync(0xffffffffu, bk, off);
                bk = (ok > bk) ? ok : bk;                 // SEL, no branch
            }
            if (lane == 0) g_cand[rbase + r] = bk;
            if (key == bk) key = 0ull;                    // remove winner
        }
    }
}

// ---------------------------------------------------------------------------
// Kernel 2: merge. One THREAD per (b,i,h) row: 8 coalesced ulonglong2 loads,
// 16 branchless compare-swap inserts into a running top-4 (named scalars,
// pure SEL). Winners' j bits union'd into the 128-bit mask.
// ---------------------------------------------------------------------------
__global__ __launch_bounds__(256) void merge_kernel()
{
    __shared__ unsigned long long s_lo, s_hi;
    const int tid = threadIdx.x;
    if (tid == 0) { s_lo = 0ull; s_hi = 0ull; }
    __syncthreads();

    const int r = blockIdx.x * blockDim.x + tid;   // 0..8191

    unsigned long long k0 = 0ull, k1 = 0ull, k2 = 0ull, k3 = 0ull;

#define INS(xx)                                                               \
    do {                                                                      \
        unsigned long long p = (xx), t;                                       \
        bool c;                                                               \
        c = p > k0; t = k0; k0 = c ? p : k0; p = c ? t : p;                   \
        c = p > k1; t = k1; k1 = c ? p : k1; p = c ? t : p;                   \
        c = p > k2; t = k2; k2 = c ? p : k2; p = c ? t : p;                   \
        c = p > k3; k3 = c ? p : k3;                                          \
    } while (0)

    const ulonglong2* c2 = (const ulonglong2*)&g_cand[(size_t)r * (NQ_ * TOPK_)];
    #pragma unroll
    for (int q = 0; q < 8; ++q) {
        const ulonglong2 c = c2[q];
        INS(c.x);
        INS(c.y);
    }
#undef INS

    unsigned long long lo = 0ull, hi = 0ull;
#define SET_BIT(kk)                                                           \
    do {                                                                      \
        const int jj = 127 - (int)((unsigned)(kk) & 0xFFFFFFFFu);             \
        if (jj < 64) lo |= 1ull << jj; else hi |= 1ull << (jj - 64);          \
    } while (0)
    SET_BIT(k0); SET_BIT(k1); SET_BIT(k2); SET_BIT(k3);
#undef SET_BIT

    if (lo) atomicOr(&s_lo, lo);
    if (hi) atomicOr(&s_hi, hi);
    __syncthreads();
    if (tid == 0) {
        if (s_lo) atomicOr(&g_maskbits[0], s_lo);
        if (s_hi) atomicOr(&g_maskbits[1], s_hi);
    }
}

// ---------------------------------------------------------------------------
// Kernel 3: fixup. Block j: if mask[j]==0, zero out[:, :, j, :]. Near-nop
// when the union mask is full (common case); exact in all cases.
// ---------------------------------------------------------------------------
__global__ __launch_bounds__(256) void fixup_kernel(float4* __restrict__ out)
{
    const int j = blockIdx.x;
    const unsigned long long w = g_maskbits[j >> 6];
    if ((w >> (j & 63)) & 1ull) return;                  // column survives

    const float4 z = make_float4(0.f, 0.f, 0.f, 0.f);
    #pragma unroll
    for (int t = 0; t < 4; ++t) {
        const int bi = threadIdx.x + t * 256;            // 0..1023
        const size_t base = ((size_t)bi * NUM_ + j) * 2; // float4 units
        out[base]     = z;
        out[base + 1] = z;
    }
}

// ---------------------------------------------------------------------------
extern "C" void kernel_launch(void* const* d_in, const int* in_sizes, int n_in,
                              void* d_out, int out_size)
{
    const float4* q4  = (const float4*)d_in[0];
    const float4* k4  = (const float4*)d_in[1];
    const float*  roi = (const float*)d_in[2];
    float*        out = (float*)d_out;

    fused_kernel<<<NROWS_ * NQ_, 256>>>(q4, k4, roi, out);  // 4096 blocks
    merge_kernel<<<(NROWS_ * H_) / 256, 256>>>();           // 32 blocks
    fixup_kernel<<<NUM_, 256>>>((float4*)out);              // 128 blocks
}

// round 16
// speedup vs baseline: 1.0213x; 1.0213x over previous
#include <cuda_runtime.h>
#include <cuda_bf16.h>

#define B_    8
#define NUM_  128
#define L_    (NUM_ * NUM_)     // 16384
#define H_    8
#define TOPK_ 4
#define NROWS_ (B_ * NUM_)      // 1024 (b,i) rows
#define NQ_    4                // quarters per row (32 j each)

// Scratch (allocation-free rule: __device__ globals)
// Candidate = packed u64: (float_bits(value) << 32) | (127 - j).
// value >= 0 (post-ReLU) so float bits are monotone; low word ties -> smaller j.
__device__ unsigned long long g_cand[NROWS_ * H_ * NQ_ * TOPK_];  // 512 KB
__device__ unsigned long long g_maskbits[2];                      // 128-bit column mask

// 256-bit streaming global load (sm_100+ / PTX 8.8): 8 consecutive floats.
__device__ __forceinline__ void ldg_v8_cs(const float* __restrict__ p,
                                          float& a0, float& a1, float& a2, float& a3,
                                          float& a4, float& a5, float& a6, float& a7)
{
    asm volatile("ld.global.cs.v8.f32 {%0,%1,%2,%3,%4,%5,%6,%7}, [%8];"
                 : "=f"(a0), "=f"(a1), "=f"(a2), "=f"(a3),
                   "=f"(a4), "=f"(a5), "=f"(a6), "=f"(a7)
                 : "l"(p));
}

// ---------------------------------------------------------------------------
// Kernel 1: block = (b,i,quarter), grid 4096. Cosine+relu for 32 j x 8 h,
// multiply by roi, write DIRECTLY to out, emit per-head per-quarter top-4
// packed candidates (branchless u64 warp-max).
// Loads are LDG.256: lane covers 16 floats of its head via 2 v8 loads per
// vector (chunks head*8+sub and head*8+sub+4; all 32B-aligned).
// ---------------------------------------------------------------------------
__global__ __launch_bounds__(256) void fused_kernel(
    const float4* __restrict__ q4, const float4* __restrict__ k4,
    const float* __restrict__ roi, float* __restrict__ out)
{
    __shared__ float s_attn[32 * 9];            // local j x head, pitch 9

    const int blk  = blockIdx.x;
    const int bi   = blk >> 2;                  // (b,i) row
    const int qtr  = blk & 3;                   // 32-j quarter
    const int tid  = threadIdx.x;
    const int warp = tid >> 5;
    const int lane = tid & 31;
    const int head = lane >> 2;
    const int sub  = lane & 3;

    if (blk == 0 && tid < 2) g_maskbits[tid] = 0ull;  // reset per replay
                                                      // (launch-boundary ordered)
    const size_t rowBase = (size_t)bi * (NUM_ * 128) + (size_t)qtr * (32 * 128);
    const int foff = head * 64 + sub * 8;       // float offset of lane's 1st chunk

    #pragma unroll
    for (int jj = 0; jj < 4; jj += 2) {
        const int jl0 = warp * 4 + jj;          // local j in [0,32)
        const float* qb0 = (const float*)(q4 + rowBase + (size_t)jl0 * 128);
        const float* kb0 = (const float*)(k4 + rowBase + (size_t)jl0 * 128);
        const float* qb1 = qb0 + 512;
        const float* kb1 = kb0 + 512;

        float q0,q1,q2,q3,q4r,q5,q6,q7, p0,p1,p2,p3,p4,p5,p6,p7;
        float c0,c1,c2,c3,c4,c5,c6,c7, d0r,d1r,d2r,d3r,d4r,d5r,d6r,d7r;

        float dot0 = 0.f, qq0 = 0.f, kk0 = 0.f;
        float dot1 = 0.f, qq1 = 0.f, kk1 = 0.f;

        // ---- j0 ----
        ldg_v8_cs(qb0 + foff,      q0,q1,q2,q3,q4r,q5,q6,q7);
        ldg_v8_cs(kb0 + foff,      c0,c1,c2,c3,c4,c5,c6,c7);
        ldg_v8_cs(qb0 + foff + 32, p0,p1,p2,p3,p4,p5,p6,p7);
        ldg_v8_cs(kb0 + foff + 32, d0r,d1r,d2r,d3r,d4r,d5r,d6r,d7r);
        dot0 += q0*c0 + q1*c1 + q2*c2 + q3*c3 + q4r*c4 + q5*c5 + q6*c6 + q7*c7;
        qq0  += q0*q0 + q1*q1 + q2*q2 + q3*q3 + q4r*q4r + q5*q5 + q6*q6 + q7*q7;
        kk0  += c0*c0 + c1*c1 + c2*c2 + c3*c3 + c4*c4 + c5*c5 + c6*c6 + c7*c7;
        dot0 += p0*d0r + p1*d1r + p2*d2r + p3*d3r + p4*d4r + p5*d5r + p6*d6r + p7*d7r;
        qq0  += p0*p0 + p1*p1 + p2*p2 + p3*p3 + p4*p4 + p5*p5 + p6*p6 + p7*p7;
        kk0  += d0r*d0r + d1r*d1r + d2r*d2r + d3r*d3r + d4r*d4r + d5r*d5r + d6r*d6r + d7r*d7r;

        // ---- j1 ----
        ldg_v8_cs(qb1 + foff,      q0,q1,q2,q3,q4r,q5,q6,q7);
        ldg_v8_cs(kb1 + foff,      c0,c1,c2,c3,c4,c5,c6,c7);
        ldg_v8_cs(qb1 + foff + 32, p0,p1,p2,p3,p4,p5,p6,p7);
        ldg_v8_cs(kb1 + foff + 32, d0r,d1r,d2r,d3r,d4r,d5r,d6r,d7r);
        dot1 += q0*c0 + q1*c1 + q2*c2 + q3*c3 + q4r*c4 + q5*c5 + q6*c6 + q7*c7;
        qq1  += q0*q0 + q1*q1 + q2*q2 + q3*q3 + q4r*q4r + q5*q5 + q6*q6 + q7*q7;
        kk1  += c0*c0 + c1*c1 + c2*c2 + c3*c3 + c4*c4 + c5*c5 + c6*c6 + c7*c7;
        dot1 += p0*d0r + p1*d1r + p2*d2r + p3*d3r + p4*d4r + p5*d5r + p6*d6r + p7*d7r;
        qq1  += p0*p0 + p1*p1 + p2*p2 + p3*p3 + p4*p4 + p5*p5 + p6*p6 + p7*p7;
        kk1  += d0r*d0r + d1r*d1r + d2r*d2r + d3r*d3r + d4r*d4r + d5r*d5r + d6r*d6r + d7r*d7r;

        #pragma unroll
        for (int off = 1; off <= 2; off <<= 1) {
            dot0 += __shfl_xor_sync(0xffffffffu, dot0, off);
            qq0  += __shfl_xor_sync(0xffffffffu, qq0,  off);
            kk0  += __shfl_xor_sync(0xffffffffu, kk0,  off);
            dot1 += __shfl_xor_sync(0xffffffffu, dot1, off);
            qq1  += __shfl_xor_sync(0xffffffffu, qq1,  off);
            kk1  += __shfl_xor_sync(0xffffffffu, kk1,  off);
        }
        if (sub == 0) {
            float e0 = fmaxf(sqrtf(qq0) * sqrtf(kk0), 1e-8f);
            float e1 = fmaxf(sqrtf(qq1) * sqrtf(kk1), 1e-8f);
            s_attn[jl0 * 9 + head]       = fmaxf(dot0 / e0, 0.0f);
            s_attn[(jl0 + 1) * 9 + head] = fmaxf(dot1 / e1, 0.0f);
        }
    }
    __syncthreads();

    // ---- writeback: out[b,i,j,h] = attn * roi[b,i,j] (mask applied later) ----
    {
        const int jl = tid >> 3;                          // local j (0..31)
        const float s = __ldg(&roi[bi * NUM_ + qtr * 32 + jl]);
        const size_t gbase = (size_t)bi * (NUM_ * H_) + (size_t)qtr * (32 * H_);
        out[gbase + tid] = s_attn[jl * 9 + (tid & 7)] * s;
    }

    // ---- per-head top-4 within this quarter (packed u64, branchless) ----
    {
        const float v = s_attn[lane * 9 + warp];          // conflict-free (pitch 9)
        const int jglob = qtr * 32 + lane;
        unsigned long long key =
            ((unsigned long long)__float_as_uint(v) << 32)
          | (unsigned long long)(unsigned)(127 - jglob);

        const int rbase = ((bi * H_ + warp) * NQ_ + qtr) * TOPK_;
        #pragma unroll
        for (int r = 0; r < TOPK_; ++r) {
            unsigned long long bk = key;
            #pragma unroll
            for (int off = 16; off > 0; off >>= 1) {
                const unsigned long long ok = __shfl_xor_sync(0xffffffffu, bk, off);
                bk = (ok > bk) ? ok : bk;                 // SEL, no branch
            }
            if (lane == 0) g_cand[rbase + r] = bk;
            if (key == bk) key = 0ull;                    // remove winner
        }
    }
}

// ---------------------------------------------------------------------------
// Kernel 2: merge. One THREAD per (b,i,h) row: 8 coalesced ulonglong2 loads,
// 16 branchless compare-swap inserts into a running top-4 (named scalars,
// pure SEL). Winners' j bits union'd into the 128-bit mask.
// ---------------------------------------------------------------------------
__global__ __launch_bounds__(256) void merge_kernel()
{
    __shared__ unsigned long long s_lo, s_hi;
    const int tid = threadIdx.x;
    if (tid == 0) { s_lo = 0ull; s_hi = 0ull; }
    __syncthreads();

    const int r = blockIdx.x * blockDim.x + tid;   // 0..8191

    unsigned long long k0 = 0ull, k1 = 0ull, k2 = 0ull, k3 = 0ull;

#define INS(xx)                                                               \
    do {                                                                      \
        unsigned long long p = (xx), t;                                       \
        bool c;                                                               \
        c = p > k0; t = k0; k0 = c ? p : k0; p = c ? t : p;                   \
        c = p > k1; t = k1; k1 = c ? p : k1; p = c ? t : p;                   \
        c = p > k2; t = k2; k2 = c ? p : k2; p = c ? t : p;                   \
        c = p > k3; k3 = c ? p : k3;                                          \
    } while (0)

    const ulonglong2* c2 = (const ulonglong2*)&g_cand[(size_t)r * (NQ_ * TOPK_)];
    #pragma unroll
    for (int q = 0; q < 8; ++q) {
        const ulonglong2 c = c2[q];
        INS(c.x);
        INS(c.y);
    }
#undef INS

    unsigned long long lo = 0ull, hi = 0ull;
#define SET_BIT(kk)                                                           \
    do {                                                                      \
        const int jj = 127 - (int)((unsigned)(kk) & 0xFFFFFFFFu);             \
        if (jj < 64) lo |= 1ull << jj; else hi |= 1ull << (jj - 64);          \
    } while (0)
    SET_BIT(k0); SET_BIT(k1); SET_BIT(k2); SET_BIT(k3);
#undef SET_BIT

    if (lo) atomicOr(&s_lo, lo);
    if (hi) atomicOr(&s_hi, hi);
    __syncthreads();
    if (tid == 0) {
        if (s_lo) atomicOr(&g_maskbits[0], s_lo);
        if (s_hi) atomicOr(&g_maskbits[1], s_hi);
    }
}

// ---------------------------------------------------------------------------
// Kernel 3: fixup. Block j: if mask[j]==0, zero out[:, :, j, :]. Near-nop
// when the union mask is full (common case); exact in all cases.
// ---------------------------------------------------------------------------
__global__ __launch_bounds__(256) void fixup_kernel(float4* __restrict__ out)
{
    const int j = blockIdx.x;
    const unsigned long long w = g_maskbits[j >> 6];
    if ((w >> (j & 63)) & 1ull) return;                  // column survives

    const float4 z = make_float4(0.f, 0.f, 0.f, 0.f);
    #pragma unroll
    for (int t = 0; t < 4; ++t) {
        const int bi = threadIdx.x + t * 256;            // 0..1023
        const size_t base = ((size_t)bi * NUM_ + j) * 2; // float4 units
        out[base]     = z;
        out[base + 1] = z;
    }
}

// ---------------------------------------------------------------------------
extern "C" void kernel_launch(void* const* d_in, const int* in_sizes, int n_in,
                              void* d_out, int out_size)
{
    const float4* q4  = (const float4*)d_in[0];
    const float4* k4  = (const float4*)d_in[1];
    const float*  roi = (const float*)d_in[2];
    float*        out = (float*)d_out;

    fused_kernel<<<NROWS_ * NQ_, 256>>>(q4, k4, roi, out);  // 4096 blocks
    merge_kernel<<<(NROWS_ * H_) / 256, 256>>>();           // 32 blocks
    fixup_kernel<<<NUM_, 256>>>((float4*)out);              // 128 blocks
}

// round 17
// speedup vs baseline: 1.0268x; 1.0054x over previous
#include <cuda_runtime.h>
#include <cuda_bf16.h>

#define B_    8
#define NUM_  128
#define L_    (NUM_ * NUM_)     // 16384
#define H_    8
#define TOPK_ 4
#define NROWS_ (B_ * NUM_)      // 1024 (b,i) rows
#define NQ_    4                // quarters per row (32 j each)

// Scratch (allocation-free rule: __device__ globals)
__device__ float    g_cval[NROWS_ * H_ * NQ_ * TOPK_];    // candidate values
__device__ unsigned g_cidx[NROWS_ * H_ * NQ_];            // packed 4x8bit local idx
__device__ unsigned g_maskbits[4];                        // 128-bit column mask

// ---------------------------------------------------------------------------
// Kernel 1: block = (b,i,quarter). Cosine+relu for 32 j x 8 h, multiply by
// roi, write DIRECTLY to out, emit per-head per-quarter top-4 candidates.
// ---------------------------------------------------------------------------
__global__ __launch_bounds__(256, 6) void fused_kernel(
    const float4* __restrict__ q4, const float4* __restrict__ k4,
    const float* __restrict__ roi, float* __restrict__ out)
{
    __shared__ float s_attn[32 * 9];            // local j x head, pitch 9

    const int blk  = blockIdx.x;
    const int bi   = blk >> 2;                  // (b,i) row
    const int qtr  = blk & 3;                   // quarter
    const int tid  = threadIdx.x;
    const int warp = tid >> 5;
    const int lane = tid & 31;
    const int head = lane >> 2;
    const int sub  = lane & 3;

    if (blk == 0 && tid < 4) g_maskbits[tid] = 0u;   // reset per replay

    const size_t rowBase = (size_t)bi * (NUM_ * 128) + (size_t)qtr * (32 * 128);

    #pragma unroll
    for (int jj = 0; jj < 4; jj += 2) {
        const int jl0 = warp * 4 + jj;          // local j in [0,32)
        const size_t base0 = rowBase + (size_t)jl0 * 128;
        const size_t base1 = base0 + 128;

        float dot0 = 0.f, qq0 = 0.f, kk0 = 0.f;
        float dot1 = 0.f, qq1 = 0.f, kk1 = 0.f;
        #pragma unroll
        for (int t = 0; t < 4; ++t) {
            const int idx = head * 16 + t * 4 + sub;
            const float4 qa = __ldcs(&q4[base0 + idx]);
            const float4 ka = __ldcs(&k4[base0 + idx]);
            const float4 qb = __ldcs(&q4[base1 + idx]);
            const float4 kb = __ldcs(&k4[base1 + idx]);
            dot0 += qa.x*ka.x + qa.y*ka.y + qa.z*ka.z + qa.w*ka.w;
            qq0  += qa.x*qa.x + qa.y*qa.y + qa.z*qa.z + qa.w*qa.w;
            kk0  += ka.x*ka.x + ka.y*ka.y + ka.z*ka.z + ka.w*ka.w;
            dot1 += qb.x*kb.x + qb.y*kb.y + qb.z*kb.z + qb.w*kb.w;
            qq1  += qb.x*qb.x + qb.y*qb.y + qb.z*qb.z + qb.w*qb.w;
            kk1  += kb.x*kb.x + kb.y*kb.y + kb.z*kb.z + kb.w*kb.w;
        }
        #pragma unroll
        for (int off = 1; off <= 2; off <<= 1) {
            dot0 += __shfl_xor_sync(0xffffffffu, dot0, off);
            qq0  += __shfl_xor_sync(0xffffffffu, qq0,  off);
            kk0  += __shfl_xor_sync(0xffffffffu, kk0,  off);
            dot1 += __shfl_xor_sync(0xffffffffu, dot1, off);
            qq1  += __shfl_xor_sync(0xffffffffu, qq1,  off);
            kk1  += __shfl_xor_sync(0xffffffffu, kk1,  off);
        }
        if (sub == 0) {
            float d0 = fmaxf(sqrtf(qq0) * sqrtf(kk0), 1e-8f);
            float d1 = fmaxf(sqrtf(qq1) * sqrtf(kk1), 1e-8f);
            s_attn[jl0 * 9 + head]       = fmaxf(dot0 / d0, 0.0f);
            s_attn[(jl0 + 1) * 9 + head] = fmaxf(dot1 / d1, 0.0f);
        }
    }
    __syncthreads();

    // ---- writeback: out[b,i,j,h] = attn * roi[b,i,j] (mask applied later) ----
    {
        const int jl = tid >> 3;                          // local j of my element
        const float s = __ldg(&roi[bi * NUM_ + qtr * 32 + jl]);
        const size_t gbase = (size_t)bi * (NUM_ * H_) + (size_t)qtr * (32 * H_);
        out[gbase + tid] = s_attn[jl * 9 + (tid & 7)] * s;
    }

    // ---- per-head top-4 within this quarter: warp w = head w ----
    {
        float v  = s_attn[lane * 9 + warp];     // conflict-free (pitch 9)
        const int jl = lane;
        unsigned packed = 0;
        const int rbase = ((bi * H_ + warp) * NQ_ + qtr) * TOPK_;
        #pragma unroll
        for (int r = 0; r < TOPK_; ++r) {
            float bv = v; int bj = jl;
            #pragma unroll
            for (int off = 16; off > 0; off >>= 1) {
                const float ov = __shfl_xor_sync(0xffffffffu, bv, off);
                const int   oj = __shfl_xor_sync(0xffffffffu, bj, off);
                if (ov > bv || (ov == bv && oj < bj)) { bv = ov; bj = oj; }
            }
            packed |= ((unsigned)bj) << (8 * r);
            if (jl == bj) v = -1e30f;           // remove winner
            if (lane == 0) g_cval[rbase + r] = bv;
        }
        if (lane == 0) g_cidx[(bi * H_ + warp) * NQ_ + qtr] = packed;
    }
}

// ---------------------------------------------------------------------------
// Kernel 2: merge. One thread per (b,i,h): top-4 of 16 candidates, union bits.
// ---------------------------------------------------------------------------
__global__ __launch_bounds__(256) void merge_kernel()
{
    __shared__ unsigned s_bits[4];
    const int tid = threadIdx.x;
    if (tid < 4) s_bits[tid] = 0u;
    __syncthreads();

    const int r = blockIdx.x * blockDim.x + tid;   // 0..8191
    float vv[16];
    int   jj[16];
    const float4* cv4 = (const float4*)&g_cval[r * NQ_ * TOPK_];
    #pragma unroll
    for (int q = 0; q < NQ_; ++q) {
        const float4 v = cv4[q];
        const unsigned w = g_cidx[r * NQ_ + q];
        vv[q*4+0] = v.x; jj[q*4+0] = q*32 + ((w      ) & 255);
        vv[q*4+1] = v.y; jj[q*4+1] = q*32 + ((w >>  8) & 255);
        vv[q*4+2] = v.z; jj[q*4+2] = q*32 + ((w >> 16) & 255);
        vv[q*4+3] = v.w; jj[q*4+3] = q*32 + ((w >> 24) & 255);
    }
    unsigned bits0 = 0, bits1 = 0, bits2 = 0, bits3 = 0;
    #pragma unroll
    for (int rr = 0; rr < TOPK_; ++rr) {
        float bv = vv[0]; int bj = jj[0]; int bt = 0;
        #pragma unroll
        for (int t = 1; t < 16; ++t)
            if (vv[t] > bv || (vv[t] == bv && jj[t] < bj)) { bv = vv[t]; bj = jj[t]; bt = t; }
        if (bj < 32)       bits0 |= 1u << bj;
        else if (bj < 64)  bits1 |= 1u << (bj - 32);
        else if (bj < 96)  bits2 |= 1u << (bj - 64);
        else               bits3 |= 1u << (bj - 96);
        vv[bt] = -1e30f;
    }
    if (bits0) atomicOr(&s_bits[0], bits0);
    if (bits1) atomicOr(&s_bits[1], bits1);
    if (bits2) atomicOr(&s_bits[2], bits2);
    if (bits3) atomicOr(&s_bits[3], bits3);
    __syncthreads();
    if (tid < 4 && s_bits[tid]) atomicOr(&g_maskbits[tid], s_bits[tid]);
}

// ---------------------------------------------------------------------------
// Kernel 3: fixup. Block j: if mask[j]==0, zero out[:, :, j, :]. Near-nop
// when the union mask is full (common case); exact in all cases.
// ---------------------------------------------------------------------------
__global__ __launch_bounds__(256) void fixup_kernel(float4* __restrict__ out)
{
    const int j = blockIdx.x;
    if ((g_maskbits[j >> 5] >> (j & 31)) & 1u) return;   // column survives

    const float4 z = make_float4(0.f, 0.f, 0.f, 0.f);
    #pragma unroll
    for (int t = 0; t < 4; ++t) {
        const int bi = threadIdx.x + t * 256;            // 0..1023
        const size_t base = ((size_t)bi * NUM_ + j) * 2; // float4 units
        out[base]     = z;
        out[base + 1] = z;
    }
}

// ---------------------------------------------------------------------------
extern "C" void kernel_launch(void* const* d_in, const int* in_sizes, int n_in,
                              void* d_out, int out_size)
{
    const float4* q4  = (const float4*)d_in[0];
    const float4* k4  = (const float4*)d_in[1];
    const float*  roi = (const float*)d_in[2];
    float*        out = (float*)d_out;

    fused_kernel<<<NROWS_ * NQ_, 256>>>(q4, k4, roi, out);  // 4096 blocks
    merge_kernel<<<(NROWS_ * H_) / 256, 256>>>();           // 32 blocks
    fixup_kernel<<<NUM_, 256>>>((float4*)out);              // 128 blocks
}